// round 10
// baseline (speedup 1.0000x reference)
#include <cuda_runtime.h>
#include <cuda_bf16.h>
#include <cstdint>

namespace {

constexpr int Dd = 160;
constexpr int Hh = 192;
constexpr int Ww = 224;
constexpr int HW = Hh * Ww;        // 43008
constexpr int N  = Dd * HW;        // 6881280

// tile: 8 x 8 x 32 outputs per block (2048), 512 threads
constexpr int TD = 8, TH = 8, TW = 32;
constexpr int MLO = 4;             // d/h halo: lo=4, hi=3
constexpr int SD = 15;             // TD + 7
constexpr int SH = 15;             // TH + 7
constexpr int SROW   = 64;         // staged floats per w-row, w in [W0-16, W0+48); 64 ≡ 0 mod 32
constexpr int SSLICE = SH * SROW;  // 960 ≡ 0 mod 32 — d/h jitter cannot shift banks
constexpr int STOT   = SD * SSLICE;// 14400 floats = 57600 B (dynamic smem)
constexpr int NROWS  = SD * SH;    // 225 staged (d,h) rows
constexpr int NTHREADS = 512;
constexpr int KPT = 4;             // k depth rows per thread (TD / 2 warp-groups)

__device__ __forceinline__ uint32_t smem_u32(const void* p) {
    return (uint32_t)__cvta_generic_to_shared(p);
}

__global__ __launch_bounds__(NTHREADS, 3)
void st3d_kernel(const float* __restrict__ img,   // (160,192,224) fp32
                 const float* __restrict__ off,   // (3,160,192,224) fp32
                 float* __restrict__ out)         // (160,192,224) fp32
{
    extern __shared__ __align__(128) float smem[];
    __shared__ __align__(8) uint64_t mbar;

    const int tid  = threadIdx.x;
    const int lane = tid & 31;
    const int warp = tid >> 5;

    const int D0 = blockIdx.z * TD;
    const int H0 = blockIdx.y * TH;
    const int W0 = blockIdx.x * TW;
    const int d_org = D0 - MLO;
    const int h_org = H0 - MLO;
    const int w_org = W0 - 16;

    // warp -> (h row, k-half): warps 0-7 do k=0..3, warps 8-15 do k=4..7
    const int h  = H0 + (warp & 7);
    const int w  = W0 + lane;
    const int kb = (warp >> 3) * KPT;
    const int base_g = (D0 + kb) * HW + h * Ww + w;

    // ---- hoist all 12 offset loads first (DRAM latency overlaps staging) ----
    const float* offD = off + base_g;
    const float* offH = off + N + base_g;
    const float* offW = off + 2 * N + base_g;
    float oD[KPT], oH[KPT], oW[KPT];
    #pragma unroll
    for (int k = 0; k < KPT; k++) {
        oD[k] = __ldg(offD + k * HW);
        oH[k] = __ldg(offH + k * HW);
        oW[k] = __ldg(offW + k * HW);
    }

    const uint32_t mb = smem_u32(&mbar);

    // w clip (uniform across the block): all boundaries are multiples of 16 floats
    const int wlo  = w_org < 0 ? 0 : w_org;
    const int whi  = (w_org + SROW) > Ww ? Ww : (w_org + SROW);
    const int head = wlo - w_org;               // 0 or 16 floats
    const int rowbytes = (whi - wlo) * 4;       // 256 or 192 B (mult of 16)

    if (tid == 0) {
        asm volatile("mbarrier.init.shared.b64 [%0], 1;" :: "r"(mb) : "memory");
        const int dlo = d_org < 0 ? 0 : d_org;
        const int dhi = (d_org + SD) > Dd ? Dd : (d_org + SD);
        const int hlo = h_org < 0 ? 0 : h_org;
        const int hhi = (h_org + SH) > Hh ? Hh : (h_org + SH);
        const uint32_t expect = (uint32_t)((dhi - dlo) * (hhi - hlo) * rowbytes);
        asm volatile("mbarrier.arrive.expect_tx.shared.b64 _, [%0], %1;"
                     :: "r"(mb), "r"(expect) : "memory");
    }
    __syncthreads();   // init+expect visible before any TMA references the barrier

    // ---- stage via cp.async.bulk: one 256B (or 192B) DMA per valid (d,h) row ----
    if (tid < NROWS) {
        const int sd = tid / SH;
        const int sh = tid - sd * SH;
        const int gd = d_org + sd;
        const int gh = h_org + sh;
        float* dstrow = smem + (sd * SH + sh) * SROW;

        if ((unsigned)gd < (unsigned)Dd && (unsigned)gh < (unsigned)Hh) {
            for (int i = 0; i < head; i++) dstrow[i] = 0.f;
            for (int i = head + (rowbytes >> 2); i < SROW; i++) dstrow[i] = 0.f;
            const float* src = img + gd * HW + gh * Ww + wlo;
            asm volatile(
                "cp.async.bulk.shared::cluster.global.mbarrier::complete_tx::bytes "
                "[%0], [%1], %2, [%3];"
                :: "r"(smem_u32(dstrow + head)), "l"(src),
                   "r"((uint32_t)rowbytes), "r"(mb)
                : "memory");
        } else {
            #pragma unroll 4
            for (int i = 0; i < SROW; i++) dstrow[i] = 0.f;
        }
    }
    __syncthreads();   // zero-fill STS visible to all threads

    // wait for all bulk DMAs (acquire orders TMA data before our LDS reads)
    {
        uint32_t done;
        asm volatile(
            "{\n\t"
            ".reg .pred p;\n\t"
            "mbarrier.try_wait.parity.acquire.cta.shared::cta.b64 p, [%1], 0;\n\t"
            "selp.b32 %0, 1, 0, p;\n\t"
            "}" : "=r"(done) : "r"(mb) : "memory");
        if (!done) {
            asm volatile(
                "{\n\t"
                ".reg .pred P1;\n\t"
                "WL_%=:\n\t"
                "mbarrier.try_wait.parity.acquire.cta.shared::cta.b64 P1, [%0], 0, 0x989680;\n\t"
                "@P1 bra.uni WD_%=;\n\t"
                "bra.uni WL_%=;\n\t"
                "WD_%=:\n\t"
                "}" :: "r"(mb) : "memory");
        }
    }

    // precomputed shifts: sX0 = floor(coord_up) - (1 + org)
    const int cd = 1 + d_org;
    const int ch = 1 + h_org;
    const int cw = 1 + w_org;
    float* outp = out + base_g;

    // ---- fully unrolled 4-way compute: 32 LDS + 4 lerp trees interleaved ----
    #pragma unroll
    for (int k = 0; k < KPT; k++) {
        const int d = D0 + kb + k;

        const float Dup = oD[k] + (float)(d + 1);
        const float Hup = oH[k] + (float)(h + 1);
        const float Wup = oW[k] + (float)(w + 1);

        const int df = __float2int_rd(Dup);
        const int hf = __float2int_rd(Hup);
        const int wf = __float2int_rd(Wup);

        const float fd = Dup - (float)df;
        const float fh = Hup - (float)hf;
        const float fw = Wup - (float)wf;

        // staged-local floor-tap coords
        const int sd0 = df - cd;
        const int sh0 = hf - ch;
        const int sw0 = wf - cw;

        float v000, v001, v010, v011, v100, v101, v110, v111;

        if ((unsigned)sd0 < (unsigned)(SD - 1) &&
            (unsigned)sh0 < (unsigned)(SH - 1) &&
            (unsigned)sw0 < (unsigned)(SROW - 1)) {
            // fast path: banks depend only on sw0 (strides ≡ 0 mod 32)
            const float* ps = smem + sd0 * SSLICE + sh0 * SROW + sw0;
            v000 = ps[0];
            v001 = ps[1];
            v010 = ps[SROW];
            v011 = ps[SROW + 1];
            v100 = ps[SSLICE];
            v101 = ps[SSLICE + 1];
            v110 = ps[SSLICE + SROW];
            v111 = ps[SSLICE + SROW + 1];
        } else {
            // rare fallback (~0.1% of lanes): gather from global
            v000 = v001 = v010 = v011 = v100 = v101 = v110 = v111 = 0.f;
            const int d0 = sd0 + d_org, h0 = sh0 + h_org, w0 = sw0 + w_org;
            const bool pd0 = (unsigned)d0 < (unsigned)Dd;
            const bool pd1 = (unsigned)(d0 + 1) < (unsigned)Dd;
            const bool ph0 = (unsigned)h0 < (unsigned)Hh;
            const bool ph1 = (unsigned)(h0 + 1) < (unsigned)Hh;
            const bool pw0 = (unsigned)w0 < (unsigned)Ww;
            const bool pw1 = (unsigned)(w0 + 1) < (unsigned)Ww;
            const int i = d0 * HW + h0 * Ww + w0;
            if (pd0 & ph0 & pw0) v000 = img[i];
            if (pd0 & ph0 & pw1) v001 = img[i + 1];
            if (pd0 & ph1 & pw0) v010 = img[i + Ww];
            if (pd0 & ph1 & pw1) v011 = img[i + Ww + 1];
            if (pd1 & ph0 & pw0) v100 = img[i + HW];
            if (pd1 & ph0 & pw1) v101 = img[i + HW + 1];
            if (pd1 & ph1 & pw0) v110 = img[i + HW + Ww];
            if (pd1 & ph1 & pw1) v111 = img[i + HW + Ww + 1];
        }

        const float a00 = v000 + fw * (v001 - v000);
        const float a01 = v010 + fw * (v011 - v010);
        const float a10 = v100 + fw * (v101 - v100);
        const float a11 = v110 + fw * (v111 - v110);

        const float b0 = a00 + fh * (a01 - a00);
        const float b1 = a10 + fh * (a11 - a10);

        outp[k * HW] = b0 + fd * (b1 - b0);
    }
}

} // namespace

extern "C" void kernel_launch(void* const* d_in, const int* in_sizes, int n_in,
                              void* d_out, int out_size)
{
    const float* img = (const float*)d_in[0];
    const float* off = (const float*)d_in[1];
    float* out = (float*)d_out;

    const int smem_bytes = STOT * (int)sizeof(float);   // 57600
    cudaFuncSetAttribute(st3d_kernel,
                         cudaFuncAttributeMaxDynamicSharedMemorySize, smem_bytes);
    cudaFuncSetAttribute(st3d_kernel,
                         cudaFuncAttributePreferredSharedMemoryCarveout, 100);

    dim3 grid(Ww / TW, Hh / TH, Dd / TD);   // (7, 24, 20) — exact
    st3d_kernel<<<grid, NTHREADS, smem_bytes>>>(img, off, out);
}

// round 11
// speedup vs baseline: 1.0072x; 1.0072x over previous
#include <cuda_runtime.h>
#include <cuda_bf16.h>
#include <cstdint>

namespace {

constexpr int Dd = 160;
constexpr int Hh = 192;
constexpr int Ww = 224;
constexpr int HW = Hh * Ww;        // 43008
constexpr int N  = Dd * HW;        // 6881280

// tile: 4 x 8 x 32 outputs per block (1024) — round-9 shape
constexpr int TD = 4, TH = 8, TW = 32;
constexpr int MLO = 4;             // d/h halo: lo=4, hi=3
constexpr int SD = 11;             // TD + 7
constexpr int SH = 15;             // TH + 7
constexpr int SROW   = 48;         // staged floats per w-row, w in [W0-8, W0+40)
constexpr int SSLICE = SH * SROW;  // 720
constexpr int STOT   = SD * SSLICE;// 7920 floats = 31680 B (static)
constexpr int NROWS  = SD * SH;    // 165 staged (d,h) rows
constexpr int NTHREADS = 256;

__device__ __forceinline__ uint32_t smem_u32(const void* p) {
    return (uint32_t)__cvta_generic_to_shared(p);
}

__global__ __launch_bounds__(NTHREADS)
void st3d_kernel(const float* __restrict__ img,   // (160,192,224) fp32
                 const float* __restrict__ off,   // (3,160,192,224) fp32
                 float* __restrict__ out)         // (160,192,224) fp32
{
    __shared__ __align__(128) float smem[STOT];
    __shared__ __align__(8) uint64_t mbar;

    const int tid  = threadIdx.x;
    const int lane = tid & 31;
    const int warp = tid >> 5;

    const int D0 = blockIdx.z * TD;
    const int H0 = blockIdx.y * TH;
    const int W0 = blockIdx.x * TW;
    const int d_org = D0 - MLO;
    const int h_org = H0 - MLO;
    const int w_org = W0 - 8;

    // warp -> one h row; thread covers all TD depth rows at (h, w)
    const int h = H0 + warp;        // TH == warps per block
    const int w = W0 + lane;
    const int base_g = D0 * HW + h * Ww + w;

    // ---- hoist all 12 offset loads first (DRAM latency overlaps staging) ----
    const float* offD = off + base_g;
    const float* offH = off + N + base_g;
    const float* offW = off + 2 * N + base_g;
    float oD[TD], oH[TD], oW[TD];
    #pragma unroll
    for (int k = 0; k < TD; k++) {
        oD[k] = __ldg(offD + k * HW);
        oH[k] = __ldg(offH + k * HW);
        oW[k] = __ldg(offW + k * HW);
    }

    const uint32_t mb = smem_u32(&mbar);

    // w clip (uniform across block): boundaries are multiples of 8 floats
    const int wlo  = w_org < 0 ? 0 : w_org;
    const int whi  = (w_org + SROW) > Ww ? Ww : (w_org + SROW);
    const int head = wlo - w_org;               // 0 or 8 floats
    const int rowbytes = (whi - wlo) * 4;       // 192 or 160 B (mult of 16)

    if (tid == 0) {
        asm volatile("mbarrier.init.shared.b64 [%0], 1;" :: "r"(mb) : "memory");
        const int dlo = d_org < 0 ? 0 : d_org;
        const int dhi = (d_org + SD) > Dd ? Dd : (d_org + SD);
        const int hlo = h_org < 0 ? 0 : h_org;
        const int hhi = (h_org + SH) > Hh ? Hh : (h_org + SH);
        const uint32_t expect = (uint32_t)((dhi - dlo) * (hhi - hlo) * rowbytes);
        asm volatile("mbarrier.arrive.expect_tx.shared.b64 _, [%0], %1;"
                     :: "r"(mb), "r"(expect) : "memory");
    }
    __syncthreads();   // init+expect visible before any TMA references the barrier

    // ---- stage via cp.async.bulk: one DMA per valid (d,h) row ----
    if (tid < NROWS) {
        const int sd = tid / SH;
        const int sh = tid - sd * SH;
        const int gd = d_org + sd;
        const int gh = h_org + sh;
        float* dstrow = smem + (sd * SH + sh) * SROW;

        if ((unsigned)gd < (unsigned)Dd && (unsigned)gh < (unsigned)Hh) {
            for (int i = 0; i < head; i++) dstrow[i] = 0.f;
            for (int i = head + (rowbytes >> 2); i < SROW; i++) dstrow[i] = 0.f;
            const float* src = img + gd * HW + gh * Ww + wlo;
            asm volatile(
                "cp.async.bulk.shared::cluster.global.mbarrier::complete_tx::bytes "
                "[%0], [%1], %2, [%3];"
                :: "r"(smem_u32(dstrow + head)), "l"(src),
                   "r"((uint32_t)rowbytes), "r"(mb)
                : "memory");
        } else {
            #pragma unroll 4
            for (int i = 0; i < SROW; i++) dstrow[i] = 0.f;
        }
    }
    __syncthreads();   // zero-fill STS visible to all threads

    // wait for all bulk DMAs
    {
        uint32_t done;
        asm volatile(
            "{\n\t"
            ".reg .pred p;\n\t"
            "mbarrier.try_wait.parity.acquire.cta.shared::cta.b64 p, [%1], 0;\n\t"
            "selp.b32 %0, 1, 0, p;\n\t"
            "}" : "=r"(done) : "r"(mb) : "memory");
        if (!done) {
            asm volatile(
                "{\n\t"
                ".reg .pred P1;\n\t"
                "WL_%=:\n\t"
                "mbarrier.try_wait.parity.acquire.cta.shared::cta.b64 P1, [%0], 0, 0x989680;\n\t"
                "@P1 bra.uni WD_%=;\n\t"
                "bra.uni WL_%=;\n\t"
                "WD_%=:\n\t"
                "}" :: "r"(mb) : "memory");
        }
    }

    // ---- compute all coords + one combined range check (no per-k branches) ----
    const int cd = 1 + d_org;
    const int ch = 1 + h_org;
    const int cw = 1 + w_org;
    float* outp = out + base_g;

    int   sd0a[TD], sh0a[TD], sw0a[TD];
    float fda[TD],  fha[TD],  fwa[TD];
    bool ok = true;
    #pragma unroll
    for (int k = 0; k < TD; k++) {
        const float Dup = oD[k] + (float)(D0 + k + 1);
        const float Hup = oH[k] + (float)(h + 1);
        const float Wup = oW[k] + (float)(w + 1);
        const int df = __float2int_rd(Dup);
        const int hf = __float2int_rd(Hup);
        const int wf = __float2int_rd(Wup);
        fda[k] = Dup - (float)df;
        fha[k] = Hup - (float)hf;
        fwa[k] = Wup - (float)wf;
        sd0a[k] = df - cd;
        sh0a[k] = hf - ch;
        sw0a[k] = wf - cw;
        ok &= ((unsigned)sd0a[k] < (unsigned)(SD - 1)) &
              ((unsigned)sh0a[k] < (unsigned)(SH - 1)) &
              ((unsigned)sw0a[k] < (unsigned)(SROW - 1));
    }

    if (ok) {
        // single straight-line fast region: 32 LDS + 4 lerp trees, one branch total
        #pragma unroll
        for (int k = 0; k < TD; k++) {
            const float* ps = smem + sd0a[k] * SSLICE + sh0a[k] * SROW + sw0a[k];
            const float v000 = ps[0];
            const float v001 = ps[1];
            const float v010 = ps[SROW];
            const float v011 = ps[SROW + 1];
            const float v100 = ps[SSLICE];
            const float v101 = ps[SSLICE + 1];
            const float v110 = ps[SSLICE + SROW];
            const float v111 = ps[SSLICE + SROW + 1];

            const float fw = fwa[k], fh = fha[k], fd = fda[k];
            const float a00 = v000 + fw * (v001 - v000);
            const float a01 = v010 + fw * (v011 - v010);
            const float a10 = v100 + fw * (v101 - v100);
            const float a11 = v110 + fw * (v111 - v110);
            const float b0 = a00 + fh * (a01 - a00);
            const float b1 = a10 + fh * (a11 - a10);
            __stcs(outp + k * HW, b0 + fd * (b1 - b0));
        }
    } else {
        // rare slow path: per-k fast/fallback (identical math to the validated path)
        #pragma unroll
        for (int k = 0; k < TD; k++) {
            const int sd0 = sd0a[k], sh0 = sh0a[k], sw0 = sw0a[k];
            float v000, v001, v010, v011, v100, v101, v110, v111;
            if ((unsigned)sd0 < (unsigned)(SD - 1) &&
                (unsigned)sh0 < (unsigned)(SH - 1) &&
                (unsigned)sw0 < (unsigned)(SROW - 1)) {
                const float* ps = smem + sd0 * SSLICE + sh0 * SROW + sw0;
                v000 = ps[0];
                v001 = ps[1];
                v010 = ps[SROW];
                v011 = ps[SROW + 1];
                v100 = ps[SSLICE];
                v101 = ps[SSLICE + 1];
                v110 = ps[SSLICE + SROW];
                v111 = ps[SSLICE + SROW + 1];
            } else {
                v000 = v001 = v010 = v011 = v100 = v101 = v110 = v111 = 0.f;
                const int d0 = sd0 + d_org, h0 = sh0 + h_org, w0 = sw0 + w_org;
                const bool pd0 = (unsigned)d0 < (unsigned)Dd;
                const bool pd1 = (unsigned)(d0 + 1) < (unsigned)Dd;
                const bool ph0 = (unsigned)h0 < (unsigned)Hh;
                const bool ph1 = (unsigned)(h0 + 1) < (unsigned)Hh;
                const bool pw0 = (unsigned)w0 < (unsigned)Ww;
                const bool pw1 = (unsigned)(w0 + 1) < (unsigned)Ww;
                const int i = d0 * HW + h0 * Ww + w0;
                if (pd0 & ph0 & pw0) v000 = img[i];
                if (pd0 & ph0 & pw1) v001 = img[i + 1];
                if (pd0 & ph1 & pw0) v010 = img[i + Ww];
                if (pd0 & ph1 & pw1) v011 = img[i + Ww + 1];
                if (pd1 & ph0 & pw0) v100 = img[i + HW];
                if (pd1 & ph0 & pw1) v101 = img[i + HW + 1];
                if (pd1 & ph1 & pw0) v110 = img[i + HW + Ww];
                if (pd1 & ph1 & pw1) v111 = img[i + HW + Ww + 1];
            }

            const float fw = fwa[k], fh = fha[k], fd = fda[k];
            const float a00 = v000 + fw * (v001 - v000);
            const float a01 = v010 + fw * (v011 - v010);
            const float a10 = v100 + fw * (v101 - v100);
            const float a11 = v110 + fw * (v111 - v110);
            const float b0 = a00 + fh * (a01 - a00);
            const float b1 = a10 + fh * (a11 - a10);
            __stcs(outp + k * HW, b0 + fd * (b1 - b0));
        }
    }
}

} // namespace

extern "C" void kernel_launch(void* const* d_in, const int* in_sizes, int n_in,
                              void* d_out, int out_size)
{
    const float* img = (const float*)d_in[0];
    const float* off = (const float*)d_in[1];
    float* out = (float*)d_out;

    // widen the smem carveout so ~6 blocks (48 warps) co-reside per SM
    cudaFuncSetAttribute(st3d_kernel,
                         cudaFuncAttributePreferredSharedMemoryCarveout, 100);

    dim3 grid(Ww / TW, Hh / TH, Dd / TD);   // (7, 24, 40) — exact
    st3d_kernel<<<grid, NTHREADS>>>(img, off, out);
}